// round 6
// baseline (speedup 1.0000x reference)
#include <cuda_runtime.h>
#include <math.h>
#include <stdint.h>

#define NN 50000
#define EE 800000
#define BN_EPS 1e-3f

// ---------------- device scratch (no allocation allowed) ----------------
// W fragment buffers: 5 k-chunks of 128x128, each 32768 floats (hi plane 16384 + lo plane 16384)
// chunk 0: prep0, 1: prep1, 2-3: upd0 (K=256), 4: upd1
__device__ float g_Wfrag[5 * 32768];
__device__ float g_bp0[128];
__device__ float g_bp1[128];
__device__ float g_bu0[128];
__device__ float g_bu1[128];

__device__ float g_bufA[NN * 128];   // intermediate activations
__device__ float g_prep[NN * 128];   // prep FFN output (per-node messages)
__device__ float g_agg[NN * 128];    // aggregated sums
__device__ float g_cnt[NN];          // per-node edge counts

// ---------------- helpers ----------------
__device__ __forceinline__ float tf32_rna(float x) {
    uint32_t u;
    asm("cvt.rna.tf32.f32 %0, %1;" : "=r"(u) : "f"(x));
    return __uint_as_float(u);
}
__device__ __forceinline__ float gelu_f(float x) {
    return 0.5f * x * (1.0f + erff(x * 0.70710678118654752f));
}
// D += A(16x8 tf32, row) * B(8x8 tf32, col)
__device__ __forceinline__ void mma_tf32(float* c, float4 a, float bx, float by) {
    asm("mma.sync.aligned.m16n8k8.row.col.f32.tf32.tf32.f32 "
        "{%0,%1,%2,%3},{%4,%5,%6,%7},{%8,%9},{%0,%1,%2,%3};"
        : "+f"(c[0]), "+f"(c[1]), "+f"(c[2]), "+f"(c[3])
        : "r"(__float_as_uint(a.x)), "r"(__float_as_uint(a.y)),
          "r"(__float_as_uint(a.z)), "r"(__float_as_uint(a.w)),
          "r"(__float_as_uint(bx)), "r"(__float_as_uint(by)));
}

// ---------------- fold W into tf32 hi/lo fragment planes ----------------
// A-operand = W'^T (M = output col, K = input dim). Entry idx within chunk:
// idx = (ks*8 + mt)*32 + lane ; a0=(r0,k0) a1=(r1,k0) a2=(r0,k1) a3=(r1,k1)
// r0 = mt*16 + lane/4, r1 = r0+8, k0 = ks*8 + lane%4, k1 = k0+4 (k local to chunk)
// hi plane at chunkbase + idx*4, lo plane at chunkbase + 16384 + idx*4.
__global__ void fold_frag(
    const float* __restrict__ W0, const float* __restrict__ g0, const float* __restrict__ v0,
    const float* __restrict__ W1, const float* __restrict__ g1, const float* __restrict__ v1,
    const float* __restrict__ W2, const float* __restrict__ g2, const float* __restrict__ v2,
    const float* __restrict__ W3, const float* __restrict__ g3, const float* __restrict__ v3) {
    int t = blockIdx.x * 256 + threadIdx.x;   // 0 .. 20479
    int chunk = t >> 12;
    int idx = t & 4095;
    const float *W, *g, *v;
    int koff;
    switch (chunk) {
        case 0:  W = W0; g = g0; v = v0; koff = 0;   break;
        case 1:  W = W1; g = g1; v = v1; koff = 0;   break;
        case 2:  W = W2; g = g2; v = v2; koff = 0;   break;
        case 3:  W = W2; g = g2; v = v2; koff = 128; break;
        default: W = W3; g = g3; v = v3; koff = 0;   break;
    }
    int lane = idx & 31;
    int mt = (idx >> 5) & 7;
    int ks = idx >> 8;
    int r0 = mt * 16 + (lane >> 2);
    int r1 = r0 + 8;
    int kg0 = koff + ks * 8 + (lane & 3);
    int kg1 = kg0 + 4;
    float s0 = g[kg0] * rsqrtf(v[kg0] + BN_EPS);
    float s1 = g[kg1] * rsqrtf(v[kg1] + BN_EPS);
    float v00 = W[kg0 * 128 + r0] * s0;   // a0
    float v10 = W[kg0 * 128 + r1] * s0;   // a1
    float v01 = W[kg1 * 128 + r0] * s1;   // a2
    float v11 = W[kg1 * 128 + r1] * s1;   // a3
    float h00 = tf32_rna(v00), h10 = tf32_rna(v10), h01 = tf32_rna(v01), h11 = tf32_rna(v11);
    float l00 = tf32_rna(v00 - h00), l10 = tf32_rna(v10 - h10);
    float l01 = tf32_rna(v01 - h01), l11 = tf32_rna(v11 - h11);
    float* base = g_Wfrag + chunk * 32768;
    *reinterpret_cast<float4*>(base + idx * 4)         = make_float4(h00, h10, h01, h11);
    *reinterpret_cast<float4*>(base + 16384 + idx * 4) = make_float4(l00, l10, l01, l11);
}

// b'[j] = bias[j] + sum_i (b_i - m_i*s_i) * W[i][j]
__global__ void fold_b_all(
    const float* __restrict__ g0, const float* __restrict__ b0, const float* __restrict__ m0, const float* __restrict__ v0, const float* __restrict__ W0, const float* __restrict__ s0, float* __restrict__ o0,
    const float* __restrict__ g1, const float* __restrict__ b1, const float* __restrict__ m1, const float* __restrict__ v1, const float* __restrict__ W1, const float* __restrict__ s1, float* __restrict__ o1,
    const float* __restrict__ g2, const float* __restrict__ b2, const float* __restrict__ m2, const float* __restrict__ v2, const float* __restrict__ W2, const float* __restrict__ s2, float* __restrict__ o2,
    const float* __restrict__ g3, const float* __restrict__ b3, const float* __restrict__ m3, const float* __restrict__ v3, const float* __restrict__ W3, const float* __restrict__ s3, float* __restrict__ o3) {
    int l = blockIdx.x;
    const float *g, *b, *m, *v, *W, *s;
    float* o;
    int K;
    switch (l) {
        case 0:  g = g0; b = b0; m = m0; v = v0; W = W0; s = s0; o = o0; K = 128; break;
        case 1:  g = g1; b = b1; m = m1; v = v1; W = W1; s = s1; o = o1; K = 128; break;
        case 2:  g = g2; b = b2; m = m2; v = v2; W = W2; s = s2; o = o2; K = 256; break;
        default: g = g3; b = b3; m = m3; v = v3; W = W3; s = s3; o = o3; K = 128; break;
    }
    int j = threadIdx.x;
    float acc0 = s[j], acc1 = 0.f;
    #pragma unroll 8
    for (int i = 0; i < K; i += 2) {
        float sc0 = g[i] * rsqrtf(v[i] + BN_EPS);
        float sc1 = g[i + 1] * rsqrtf(v[i + 1] + BN_EPS);
        acc0 = fmaf(b[i] - m[i] * sc0, W[i * 128 + j], acc0);
        acc1 = fmaf(b[i + 1] - m[i + 1] * sc1, W[(i + 1) * 128 + j], acc1);
    }
    o[j] = acc0 + acc1;
}

// ---------------- zero agg + cnt ----------------
__global__ void zero_kernel() {
    int i = blockIdx.x * 256 + threadIdx.x;
    float4 z = make_float4(0.f, 0.f, 0.f, 0.f);
    if (i < NN * 128 / 4) reinterpret_cast<float4*>(g_agg)[i] = z;
    if (i < NN / 4)       reinterpret_cast<float4*>(g_cnt)[i] = z;
}

// ---------------- tensor-core GEMM + bias + gelu (3xTF32) ----------------
// Y[nrows,128] = gelu(X @ W' + b'), X chunked in 128-wide K pieces.
// Block: 256 threads, tile = 128 x-rows (N dim of mma) x 128 w-cols (M dim).
// Warps: mg = wid&3 (M stripe of 32 = 2 m-tiles), ng = wid>>2 (N stripe of 64 = 8 n-tiles).
// A (= W'^T) fragments from gmem (L2-hot), double-buffered across k-steps.
// B (= x^T) fragments from smem, repacked per chunk: entry {b0h,b1h,b0l,b1l} per lane.
template <int CHUNKS, bool CONCAT>
__global__ void __launch_bounds__(256, 1)
gemm_tc(const float* __restrict__ X0, const float* __restrict__ Wfrag,
        const float* __restrict__ B, float* __restrict__ Y, int nrows) {
    constexpr int LDX = 132;
    extern __shared__ float sm[];
    float* xs = sm;                   // 128 * 132 row-major staging
    float* xf = sm + 128 * LDX;       // 8192 entries * 4 floats = 32768

    const int tid = threadIdx.x;
    const int lane = tid & 31;
    const int wid = tid >> 5;
    const int mg = wid & 3;           // M group (w-cols)
    const int ng = wid >> 2;          // N group (x-rows)
    const int row0 = blockIdx.x * 128;

    float c[2][8][4];
    #pragma unroll
    for (int mt = 0; mt < 2; mt++)
        #pragma unroll
        for (int nt = 0; nt < 8; nt++)
            #pragma unroll
            for (int j = 0; j < 4; j++) c[mt][nt][j] = 0.f;

    for (int cc = 0; cc < CHUNKS; cc++) {
        if (cc) __syncthreads();
        // ---- stage x rows (coalesced) ----
        {
            const float* Xc = (CONCAT && cc == 1) ? g_agg : X0;
            #pragma unroll
            for (int idx = tid; idx < 128 * 32; idx += 256) {
                int r = idx >> 5, k4 = idx & 31;
                int row = row0 + r;
                float4 v = make_float4(0.f, 0.f, 0.f, 0.f);
                if (row < nrows) {
                    v = reinterpret_cast<const float4*>(Xc + (size_t)row * 128)[k4];
                    if (CONCAT && cc == 1) {
                        float cn = g_cnt[row];
                        float f = (cn > 0.f) ? (1.0f / cn) : 0.f;
                        v.x *= f; v.y *= f; v.z *= f; v.w *= f;
                    }
                }
                *reinterpret_cast<float4*>(xs + r * LDX + k4 * 4) = v;
            }
        }
        __syncthreads();
        // ---- repack to B fragments with tf32 hi/lo split ----
        // entry e: lane_e = e&31, nt = (e>>5)&15, ks = e>>9
        // b0 = x[nt*8 + lane_e/4][ks*8 + lane_e%4], b1 = same k+4
        #pragma unroll
        for (int e = tid; e < 8192; e += 256) {
            int le = e & 31, nt = (e >> 5) & 15, ks = e >> 9;
            int r = nt * 8 + (le >> 2);
            int k = ks * 8 + (le & 3);
            float v0 = xs[r * LDX + k];
            float v1 = xs[r * LDX + k + 4];
            float h0 = tf32_rna(v0), h1 = tf32_rna(v1);
            float l0 = tf32_rna(v0 - h0), l1 = tf32_rna(v1 - h1);
            *reinterpret_cast<float4*>(xf + e * 4) = make_float4(h0, h1, l0, l1);
        }
        __syncthreads();

        // ---- mainloop: 16 k-steps, A double-buffered from gmem ----
        const float* Wc = Wfrag + cc * 32768;
        float4 ah[2], al[2], ahn[2], aln[2];
        #pragma unroll
        for (int mt = 0; mt < 2; mt++) {
            int aidx = (mg * 2 + mt) * 32 + lane;   // ks = 0
            ah[mt] = __ldg(reinterpret_cast<const float4*>(Wc + aidx * 4));
            al[mt] = __ldg(reinterpret_cast<const float4*>(Wc + 16384 + aidx * 4));
        }
        #pragma unroll 1
        for (int ks = 0; ks < 16; ks++) {
            if (ks < 15) {
                #pragma unroll
                for (int mt = 0; mt < 2; mt++) {
                    int aidx = ((ks + 1) * 8 + mg * 2 + mt) * 32 + lane;
                    ahn[mt] = __ldg(reinterpret_cast<const float4*>(Wc + aidx * 4));
                    aln[mt] = __ldg(reinterpret_cast<const float4*>(Wc + 16384 + aidx * 4));
                }
            }
            #pragma unroll
            for (int nt = 0; nt < 8; nt++) {
                float4 b = *reinterpret_cast<const float4*>(
                    xf + ((ks * 16 + ng * 8 + nt) * 32 + lane) * 4);
                #pragma unroll
                for (int mt = 0; mt < 2; mt++) {
                    mma_tf32(c[mt][nt], ah[mt], b.x, b.y);  // Ah * Bh
                    mma_tf32(c[mt][nt], ah[mt], b.z, b.w);  // Ah * Bl
                    mma_tf32(c[mt][nt], al[mt], b.x, b.y);  // Al * Bh
                }
            }
            #pragma unroll
            for (int mt = 0; mt < 2; mt++) { ah[mt] = ahn[mt]; al[mt] = aln[mt]; }
        }
    }

    // ---- epilogue: bias + gelu + transposed store ----
    // C tile (mt, nt): M = w-col, N = x-row.
    // c0 -> Y[rowx][col0], c1 -> Y[rowx+1][col0], c2 -> Y[rowx][col0+8], c3 -> Y[rowx+1][col0+8]
    #pragma unroll
    for (int mt = 0; mt < 2; mt++) {
        int col0 = mg * 32 + mt * 16 + (lane >> 2);
        float bb0 = B[col0];
        float bb8 = B[col0 + 8];
        #pragma unroll
        for (int nt = 0; nt < 8; nt++) {
            int rowx = row0 + ng * 64 + nt * 8 + 2 * (lane & 3);
            if (rowx < nrows) {
                Y[(size_t)rowx * 128 + col0]     = gelu_f(c[mt][nt][0] + bb0);
                Y[(size_t)rowx * 128 + col0 + 8] = gelu_f(c[mt][nt][2] + bb8);
            }
            if (rowx + 1 < nrows) {
                Y[(size_t)(rowx + 1) * 128 + col0]     = gelu_f(c[mt][nt][1] + bb0);
                Y[(size_t)(rowx + 1) * 128 + col0 + 8] = gelu_f(c[mt][nt][3] + bb8);
            }
        }
    }
}

// ---------------- edge scatter: 4 edges per warp, loads batched for MLP ----------------
__global__ void __launch_bounds__(256)
scatter_kernel(const int* __restrict__ edges, const float* __restrict__ ew) {
    int warp = blockIdx.x * 8 + (threadIdx.x >> 5);
    int lane = threadIdx.x & 31;
    int e0 = warp * 4;

    int dst[4], src[4];
    float w[4];
    #pragma unroll
    for (int t = 0; t < 4; t++) {
        dst[t] = __ldg(edges + e0 + t);
        src[t] = __ldg(edges + EE + e0 + t);
        w[t]   = __ldg(ew + e0 + t);
    }
    float4 v[4];
    #pragma unroll
    for (int t = 0; t < 4; t++)
        v[t] = __ldg(reinterpret_cast<const float4*>(g_prep + (size_t)src[t] * 128) + lane);
    #pragma unroll
    for (int t = 0; t < 4; t++) {
        v[t].x *= w[t]; v[t].y *= w[t]; v[t].z *= w[t]; v[t].w *= w[t];
        float* dp = g_agg + (size_t)dst[t] * 128 + lane * 4;
        asm volatile("red.global.add.v4.f32 [%0], {%1, %2, %3, %4};"
                     :: "l"(dp), "f"(v[t].x), "f"(v[t].y), "f"(v[t].z), "f"(v[t].w) : "memory");
    }
    if (lane < 4) {
        asm volatile("red.global.add.f32 [%0], %1;"
                     :: "l"(g_cnt + dst[lane]), "f"(1.0f) : "memory");
    }
}

// ---------------- launch ----------------
extern "C" void kernel_launch(void* const* d_in, const int* in_sizes, int n_in,
                              void* d_out, int out_size) {
    const float* node_repr = (const float*)d_in[0];
    const int*   edges     = (const int*)d_in[1];
    const float* edge_w    = (const float*)d_in[2];

    const float* p0g = (const float*)d_in[3];  const float* p0b = (const float*)d_in[4];
    const float* p0m = (const float*)d_in[5];  const float* p0v = (const float*)d_in[6];
    const float* p0W = (const float*)d_in[7];  const float* p0bias = (const float*)d_in[8];
    const float* p1g = (const float*)d_in[9];  const float* p1b = (const float*)d_in[10];
    const float* p1m = (const float*)d_in[11]; const float* p1v = (const float*)d_in[12];
    const float* p1W = (const float*)d_in[13]; const float* p1bias = (const float*)d_in[14];
    const float* u0g = (const float*)d_in[15]; const float* u0b = (const float*)d_in[16];
    const float* u0m = (const float*)d_in[17]; const float* u0v = (const float*)d_in[18];
    const float* u0W = (const float*)d_in[19]; const float* u0bias = (const float*)d_in[20];
    const float* u1g = (const float*)d_in[21]; const float* u1b = (const float*)d_in[22];
    const float* u1m = (const float*)d_in[23]; const float* u1v = (const float*)d_in[24];
    const float* u1W = (const float*)d_in[25]; const float* u1bias = (const float*)d_in[26];

    float *pWfrag, *pbp0, *pbp1, *pbu0, *pbu1, *pBufA, *pPrep;
    cudaGetSymbolAddress((void**)&pWfrag, g_Wfrag);
    cudaGetSymbolAddress((void**)&pbp0, g_bp0);
    cudaGetSymbolAddress((void**)&pbp1, g_bp1);
    cudaGetSymbolAddress((void**)&pbu0, g_bu0);
    cudaGetSymbolAddress((void**)&pbu1, g_bu1);
    cudaGetSymbolAddress((void**)&pBufA, g_bufA);
    cudaGetSymbolAddress((void**)&pPrep, g_prep);

    const int smemB = (128 * 132 + 32768) * 4;   // 198656 B
    cudaFuncSetAttribute(gemm_tc<1, false>, cudaFuncAttributeMaxDynamicSharedMemorySize, smemB);
    cudaFuncSetAttribute(gemm_tc<2, true>,  cudaFuncAttributeMaxDynamicSharedMemorySize, smemB);

    // 1) fold BN + tf32 hi/lo split into W fragment planes, fold biases
    fold_frag<<<80, 256>>>(p0W, p0g, p0v,
                           p1W, p1g, p1v,
                           u0W, u0g, u0v,
                           u1W, u1g, u1v);
    fold_b_all<<<4, 128>>>(p0g, p0b, p0m, p0v, p0W, p0bias, pbp0,
                           p1g, p1b, p1m, p1v, p1W, p1bias, pbp1,
                           u0g, u0b, u0m, u0v, u0W, u0bias, pbu0,
                           u1g, u1b, u1m, u1v, u1W, u1bias, pbu1);

    // 2) zero aggregation buffers
    zero_kernel<<<(NN * 128 / 4 + 255) / 256, 256>>>();

    const int gblocks = (NN + 127) / 128;  // 391
    // 3) prepare FFN per NODE (16x algebraic reduction vs per-edge)
    gemm_tc<1, false><<<gblocks, 256, smemB>>>(node_repr, pWfrag,          pbp0, pBufA, NN);
    gemm_tc<1, false><<<gblocks, 256, smemB>>>(pBufA,     pWfrag + 32768,  pbp1, pPrep, NN);

    // 4) scatter-aggregate along edges
    scatter_kernel<<<EE / 32, 256>>>(edges, edge_w);

    // 5) update FFN: concat(node_repr, agg_mean) -> H, then H -> H (writes d_out)
    gemm_tc<2, true><<<gblocks, 256, smemB>>>(node_repr, pWfrag + 65536,  pbu0, pBufA, NN);
    gemm_tc<1, false><<<gblocks, 256, smemB>>>(pBufA,    pWfrag + 131072, pbu1, (float*)d_out, NN);
}

// round 7
// speedup vs baseline: 1.0721x; 1.0721x over previous
#include <cuda_runtime.h>
#include <math.h>
#include <stdint.h>

#define NN 50000
#define EE 800000
#define BN_EPS 1e-3f

// ---------------- device scratch (no allocation allowed) ----------------
// W fragment buffers: 10 K64-chunks of [64k x 128m], each 16384 floats
// (hi plane 8192 + lo plane 8192).
// chunks 0-1: prep0, 2-3: prep1, 4-7: upd0 (K=256), 8-9: upd1
__device__ float g_Wfrag[10 * 16384];
__device__ float g_bp0[128];
__device__ float g_bp1[128];
__device__ float g_bu0[128];
__device__ float g_bu1[128];

__device__ float g_bufA[NN * 128];   // intermediate activations
__device__ float g_prep[NN * 128];   // prep FFN output (per-node messages)
__device__ float g_agg[NN * 128];    // aggregated sums
__device__ float g_cnt[NN];          // per-node edge counts

// ---------------- helpers ----------------
__device__ __forceinline__ float tf32_rna(float x) {
    uint32_t u;
    asm("cvt.rna.tf32.f32 %0, %1;" : "=r"(u) : "f"(x));
    return __uint_as_float(u);
}
__device__ __forceinline__ float gelu_f(float x) {
    return 0.5f * x * (1.0f + erff(x * 0.70710678118654752f));
}
// D += A(16x8 tf32, row) * B(8x8 tf32, col)
__device__ __forceinline__ void mma_tf32(float* c, float4 a, float bx, float by) {
    asm("mma.sync.aligned.m16n8k8.row.col.f32.tf32.tf32.f32 "
        "{%0,%1,%2,%3},{%4,%5,%6,%7},{%8,%9},{%0,%1,%2,%3};"
        : "+f"(c[0]), "+f"(c[1]), "+f"(c[2]), "+f"(c[3])
        : "r"(__float_as_uint(a.x)), "r"(__float_as_uint(a.y)),
          "r"(__float_as_uint(a.z)), "r"(__float_as_uint(a.w)),
          "r"(__float_as_uint(bx)), "r"(__float_as_uint(by)));
}

// ---------------- fold W into tf32 hi/lo fragment planes (K64 chunks) ----------------
// Entry idx within chunk: idx = (ks*8 + mt)*32 + lane, ks,mt in 0..7.
// a0=(r0,k0) a1=(r1,k0) a2=(r0,k1) a3=(r1,k1);
// r0 = mt*16 + lane/4, r1 = r0+8, k0 = ks*8 + lane%4 (chunk-local), k1 = k0+4.
// hi plane at chunkbase + idx*4, lo plane at chunkbase + 8192 + idx*4.
__global__ void fold_frag(
    const float* __restrict__ W0, const float* __restrict__ g0, const float* __restrict__ v0,
    const float* __restrict__ W1, const float* __restrict__ g1, const float* __restrict__ v1,
    const float* __restrict__ W2, const float* __restrict__ g2, const float* __restrict__ v2,
    const float* __restrict__ W3, const float* __restrict__ g3, const float* __restrict__ v3) {
    int t = blockIdx.x * 256 + threadIdx.x;   // 0 .. 20479
    int chunk = t >> 11;                      // 0..9
    int idx = t & 2047;
    const float *W, *g, *v;
    int koff;
    if (chunk < 2)      { W = W0; g = g0; v = v0; koff = chunk * 64; }
    else if (chunk < 4) { W = W1; g = g1; v = v1; koff = (chunk - 2) * 64; }
    else if (chunk < 8) { W = W2; g = g2; v = v2; koff = (chunk - 4) * 64; }
    else                { W = W3; g = g3; v = v3; koff = (chunk - 8) * 64; }
    int lane = idx & 31;
    int mt = (idx >> 5) & 7;
    int ks = idx >> 8;                        // 0..7
    int r0 = mt * 16 + (lane >> 2);
    int r1 = r0 + 8;
    int kg0 = koff + ks * 8 + (lane & 3);
    int kg1 = kg0 + 4;
    float s0 = g[kg0] * rsqrtf(v[kg0] + BN_EPS);
    float s1 = g[kg1] * rsqrtf(v[kg1] + BN_EPS);
    float v00 = W[kg0 * 128 + r0] * s0;   // a0
    float v10 = W[kg0 * 128 + r1] * s0;   // a1
    float v01 = W[kg1 * 128 + r0] * s1;   // a2
    float v11 = W[kg1 * 128 + r1] * s1;   // a3
    float h00 = tf32_rna(v00), h10 = tf32_rna(v10), h01 = tf32_rna(v01), h11 = tf32_rna(v11);
    float l00 = tf32_rna(v00 - h00), l10 = tf32_rna(v10 - h10);
    float l01 = tf32_rna(v01 - h01), l11 = tf32_rna(v11 - h11);
    float* base = g_Wfrag + chunk * 16384;
    *reinterpret_cast<float4*>(base + idx * 4)        = make_float4(h00, h10, h01, h11);
    *reinterpret_cast<float4*>(base + 8192 + idx * 4) = make_float4(l00, l10, l01, l11);
}

// b'[j] = bias[j] + sum_i (b_i - m_i*s_i) * W[i][j]
__global__ void fold_b_all(
    const float* __restrict__ g0, const float* __restrict__ b0, const float* __restrict__ m0, const float* __restrict__ v0, const float* __restrict__ W0, const float* __restrict__ s0, float* __restrict__ o0,
    const float* __restrict__ g1, const float* __restrict__ b1, const float* __restrict__ m1, const float* __restrict__ v1, const float* __restrict__ W1, const float* __restrict__ s1, float* __restrict__ o1,
    const float* __restrict__ g2, const float* __restrict__ b2, const float* __restrict__ m2, const float* __restrict__ v2, const float* __restrict__ W2, const float* __restrict__ s2, float* __restrict__ o2,
    const float* __restrict__ g3, const float* __restrict__ b3, const float* __restrict__ m3, const float* __restrict__ v3, const float* __restrict__ W3, const float* __restrict__ s3, float* __restrict__ o3) {
    int l = blockIdx.x;
    const float *g, *b, *m, *v, *W, *s;
    float* o;
    int K;
    switch (l) {
        case 0:  g = g0; b = b0; m = m0; v = v0; W = W0; s = s0; o = o0; K = 128; break;
        case 1:  g = g1; b = b1; m = m1; v = v1; W = W1; s = s1; o = o1; K = 128; break;
        case 2:  g = g2; b = b2; m = m2; v = v2; W = W2; s = s2; o = o2; K = 256; break;
        default: g = g3; b = b3; m = m3; v = v3; W = W3; s = s3; o = o3; K = 128; break;
    }
    int j = threadIdx.x;
    float acc0 = s[j], acc1 = 0.f;
    #pragma unroll 8
    for (int i = 0; i < K; i += 2) {
        float sc0 = g[i] * rsqrtf(v[i] + BN_EPS);
        float sc1 = g[i + 1] * rsqrtf(v[i + 1] + BN_EPS);
        acc0 = fmaf(b[i] - m[i] * sc0, W[i * 128 + j], acc0);
        acc1 = fmaf(b[i + 1] - m[i + 1] * sc1, W[(i + 1) * 128 + j], acc1);
    }
    o[j] = acc0 + acc1;
}

// ---------------- zero agg + cnt ----------------
__global__ void zero_kernel() {
    int i = blockIdx.x * 256 + threadIdx.x;
    float4 z = make_float4(0.f, 0.f, 0.f, 0.f);
    if (i < NN * 128 / 4) reinterpret_cast<float4*>(g_agg)[i] = z;
    if (i < NN / 4)       reinterpret_cast<float4*>(g_cnt)[i] = z;
}

// ---------------- tensor-core GEMM + bias + gelu (3xTF32, all-smem mainloop) ------
// Y[nrows,128] = gelu(X @ W' + b'), K processed in 64-wide chunks.
// Block: 256 threads, tile = 128 x-rows (N) x 128 w-cols (M).
// Warps: mg = wid&3 (M stripe of 32 = 2 m-tiles), ng = wid>>2 (N stripe of 64 = 8 n-tiles).
// Per chunk: bulk-copy W frag chunk (gmem, already fragment-ordered) into smem ws;
// stage x rows into xs; repack to B fragments xf with hi/lo split. Mainloop: pure LDS.
template <int CHUNKS, bool CONCAT>
__global__ void __launch_bounds__(256, 1)
gemm_tc(const float* __restrict__ X0, const float* __restrict__ Wfrag,
        const float* __restrict__ B, float* __restrict__ Y, int nrows) {
    constexpr int LDS_X = 68;            // floats per staged x row (272B)
    extern __shared__ float sm[];
    float* ws = sm;                      // 16384 floats: W frag chunk (hi 8192 | lo 8192)
    float* xf = sm + 16384;              // 16384 floats: 4096 B-frag entries {b0h,b1h,b0l,b1l}
    float* xs = sm + 32768;              // 128 * 68 staging

    const int tid = threadIdx.x;
    const int lane = tid & 31;
    const int wid = tid >> 5;
    const int mg = wid & 3;              // M group (w-cols)
    const int ng = wid >> 2;             // N group (x-rows)
    const int row0 = blockIdx.x * 128;

    float c[2][8][4];
    #pragma unroll
    for (int mt = 0; mt < 2; mt++)
        #pragma unroll
        for (int nt = 0; nt < 8; nt++)
            #pragma unroll
            for (int j = 0; j < 4; j++) c[mt][nt][j] = 0.f;

    for (int cc = 0; cc < CHUNKS; cc++) {
        if (cc) __syncthreads();
        // ---- bulk-copy W frag chunk into smem (coalesced, fragment-ordered) ----
        {
            const float4* Wg = reinterpret_cast<const float4*>(Wfrag + cc * 16384);
            float4* Ws4 = reinterpret_cast<float4*>(ws);
            #pragma unroll
            for (int i = tid; i < 4096; i += 256) Ws4[i] = Wg[i];
        }
        // ---- stage x rows (coalesced, 64 k-columns of the source) ----
        {
            const float* Xc = (CONCAT && cc >= 2) ? g_agg : X0;
            const int koff = (cc & 1) * 64;
            #pragma unroll
            for (int idx = tid; idx < 128 * 16; idx += 256) {
                int r = idx >> 4, k4 = idx & 15;
                int row = row0 + r;
                float4 v = make_float4(0.f, 0.f, 0.f, 0.f);
                if (row < nrows) {
                    v = reinterpret_cast<const float4*>(Xc + (size_t)row * 128 + koff)[k4];
                    if (CONCAT && cc >= 2) {
                        float cn = g_cnt[row];
                        float f = (cn > 0.f) ? (1.0f / cn) : 0.f;
                        v.x *= f; v.y *= f; v.z *= f; v.w *= f;
                    }
                }
                *reinterpret_cast<float4*>(xs + r * LDS_X + k4 * 4) = v;
            }
        }
        __syncthreads();
        // ---- repack to B fragments with tf32 hi/lo split ----
        // entry e: le = e&31, nt = (e>>5)&15, ks = e>>9 (0..7)
        // b0 = x[nt*8 + le/4][ks*8 + le%4], b1 = same k+4
        #pragma unroll
        for (int e = tid; e < 4096; e += 256) {
            int le = e & 31, nt = (e >> 5) & 15, ks = e >> 9;
            int r = nt * 8 + (le >> 2);
            int k = ks * 8 + (le & 3);
            float v0 = xs[r * LDS_X + k];
            float v1 = xs[r * LDS_X + k + 4];
            float h0 = tf32_rna(v0), h1 = tf32_rna(v1);
            float l0 = tf32_rna(v0 - h0), l1 = tf32_rna(v1 - h1);
            *reinterpret_cast<float4*>(xf + e * 4) = make_float4(h0, h1, l0, l1);
        }
        __syncthreads();

        // ---- mainloop: 8 k-steps, A and B both from smem ----
        #pragma unroll
        for (int ks = 0; ks < 8; ks++) {
            float4 ah[2], al[2];
            #pragma unroll
            for (int mt = 0; mt < 2; mt++) {
                int aidx = (ks * 8 + mg * 2 + mt) * 32 + lane;
                ah[mt] = *reinterpret_cast<const float4*>(ws + aidx * 4);
                al[mt] = *reinterpret_cast<const float4*>(ws + 8192 + aidx * 4);
            }
            #pragma unroll
            for (int nt = 0; nt < 8; nt++) {
                float4 b = *reinterpret_cast<const float4*>(
                    xf + ((ks * 16 + ng * 8 + nt) * 32 + lane) * 4);
                #pragma unroll
                for (int mt = 0; mt < 2; mt++) {
                    mma_tf32(c[mt][nt], ah[mt], b.x, b.y);  // Ah * Bh
                    mma_tf32(c[mt][nt], ah[mt], b.z, b.w);  // Ah * Bl
                    mma_tf32(c[mt][nt], al[mt], b.x, b.y);  // Al * Bh
                }
            }
        }
    }

    // ---- epilogue: bias + gelu + transposed store ----
    #pragma unroll
    for (int mt = 0; mt < 2; mt++) {
        int col0 = mg * 32 + mt * 16 + (lane >> 2);
        float bb0 = B[col0];
        float bb8 = B[col0 + 8];
        #pragma unroll
        for (int nt = 0; nt < 8; nt++) {
            int rowx = row0 + ng * 64 + nt * 8 + 2 * (lane & 3);
            if (rowx < nrows) {
                Y[(size_t)rowx * 128 + col0]     = gelu_f(c[mt][nt][0] + bb0);
                Y[(size_t)rowx * 128 + col0 + 8] = gelu_f(c[mt][nt][2] + bb8);
            }
            if (rowx + 1 < nrows) {
                Y[(size_t)(rowx + 1) * 128 + col0]     = gelu_f(c[mt][nt][1] + bb0);
                Y[(size_t)(rowx + 1) * 128 + col0 + 8] = gelu_f(c[mt][nt][3] + bb8);
            }
        }
    }
}

// ---------------- edge scatter: 4 edges per warp, loads batched for MLP ----------------
__global__ void __launch_bounds__(256)
scatter_kernel(const int* __restrict__ edges, const float* __restrict__ ew) {
    int warp = blockIdx.x * 8 + (threadIdx.x >> 5);
    int lane = threadIdx.x & 31;
    int e0 = warp * 4;

    int dst[4], src[4];
    float w[4];
    #pragma unroll
    for (int t = 0; t < 4; t++) {
        dst[t] = __ldg(edges + e0 + t);
        src[t] = __ldg(edges + EE + e0 + t);
        w[t]   = __ldg(ew + e0 + t);
    }
    float4 v[4];
    #pragma unroll
    for (int t = 0; t < 4; t++)
        v[t] = __ldg(reinterpret_cast<const float4*>(g_prep + (size_t)src[t] * 128) + lane);
    #pragma unroll
    for (int t = 0; t < 4; t++) {
        v[t].x *= w[t]; v[t].y *= w[t]; v[t].z *= w[t]; v[t].w *= w[t];
        float* dp = g_agg + (size_t)dst[t] * 128 + lane * 4;
        asm volatile("red.global.add.v4.f32 [%0], {%1, %2, %3, %4};"
                     :: "l"(dp), "f"(v[t].x), "f"(v[t].y), "f"(v[t].z), "f"(v[t].w) : "memory");
    }
    if (lane < 4) {
        asm volatile("red.global.add.f32 [%0], %1;"
                     :: "l"(g_cnt + dst[lane]), "f"(1.0f) : "memory");
    }
}

// ---------------- launch ----------------
extern "C" void kernel_launch(void* const* d_in, const int* in_sizes, int n_in,
                              void* d_out, int out_size) {
    const float* node_repr = (const float*)d_in[0];
    const int*   edges     = (const int*)d_in[1];
    const float* edge_w    = (const float*)d_in[2];

    const float* p0g = (const float*)d_in[3];  const float* p0b = (const float*)d_in[4];
    const float* p0m = (const float*)d_in[5];  const float* p0v = (const float*)d_in[6];
    const float* p0W = (const float*)d_in[7];  const float* p0bias = (const float*)d_in[8];
    const float* p1g = (const float*)d_in[9];  const float* p1b = (const float*)d_in[10];
    const float* p1m = (const float*)d_in[11]; const float* p1v = (const float*)d_in[12];
    const float* p1W = (const float*)d_in[13]; const float* p1bias = (const float*)d_in[14];
    const float* u0g = (const float*)d_in[15]; const float* u0b = (const float*)d_in[16];
    const float* u0m = (const float*)d_in[17]; const float* u0v = (const float*)d_in[18];
    const float* u0W = (const float*)d_in[19]; const float* u0bias = (const float*)d_in[20];
    const float* u1g = (const float*)d_in[21]; const float* u1b = (const float*)d_in[22];
    const float* u1m = (const float*)d_in[23]; const float* u1v = (const float*)d_in[24];
    const float* u1W = (const float*)d_in[25]; const float* u1bias = (const float*)d_in[26];

    float *pWfrag, *pbp0, *pbp1, *pbu0, *pbu1, *pBufA, *pPrep;
    cudaGetSymbolAddress((void**)&pWfrag, g_Wfrag);
    cudaGetSymbolAddress((void**)&pbp0, g_bp0);
    cudaGetSymbolAddress((void**)&pbp1, g_bp1);
    cudaGetSymbolAddress((void**)&pbu0, g_bu0);
    cudaGetSymbolAddress((void**)&pbu1, g_bu1);
    cudaGetSymbolAddress((void**)&pBufA, g_bufA);
    cudaGetSymbolAddress((void**)&pPrep, g_prep);

    const int smemB = (16384 + 16384 + 128 * 68) * 4;   // 165888 B
    cudaFuncSetAttribute(gemm_tc<2, false>, cudaFuncAttributeMaxDynamicSharedMemorySize, smemB);
    cudaFuncSetAttribute(gemm_tc<4, true>,  cudaFuncAttributeMaxDynamicSharedMemorySize, smemB);

    // 1) fold BN + tf32 hi/lo split into K64-chunk fragment planes, fold biases
    fold_frag<<<80, 256>>>(p0W, p0g, p0v,
                           p1W, p1g, p1v,
                           u0W, u0g, u0v,
                           u1W, u1g, u1v);
    fold_b_all<<<4, 128>>>(p0g, p0b, p0m, p0v, p0W, p0bias, pbp0,
                           p1g, p1b, p1m, p1v, p1W, p1bias, pbp1,
                           u0g, u0b, u0m, u0v, u0W, u0bias, pbu0,
                           u1g, u1b, u1m, u1v, u1W, u1bias, pbu1);

    // 2) zero aggregation buffers
    zero_kernel<<<(NN * 128 / 4 + 255) / 256, 256>>>();

    const int gblocks = (NN + 127) / 128;  // 391
    // 3) prepare FFN per NODE (16x algebraic reduction vs per-edge)
    gemm_tc<2, false><<<gblocks, 256, smemB>>>(node_repr, pWfrag,              pbp0, pBufA, NN);
    gemm_tc<2, false><<<gblocks, 256, smemB>>>(pBufA,     pWfrag + 2 * 16384,  pbp1, pPrep, NN);

    // 4) scatter-aggregate along edges
    scatter_kernel<<<EE / 32, 256>>>(edges, edge_w);

    // 5) update FFN: concat(node_repr, agg_mean) -> H, then H -> H (writes d_out)
    gemm_tc<4, true><<<gblocks, 256, smemB>>>(node_repr, pWfrag + 4 * 16384,  pbu0, pBufA, NN);
    gemm_tc<2, false><<<gblocks, 256, smemB>>>(pBufA,    pWfrag + 8 * 16384,  pbu1, (float*)d_out, NN);
}

// round 9
// speedup vs baseline: 1.1874x; 1.1075x over previous
#include <cuda_runtime.h>
#include <math.h>
#include <stdint.h>

#define NN 50000
#define EE 800000
#define BN_EPS 1e-3f

// ---------------- device scratch (no allocation allowed) ----------------
// W fragment buffers: 20 K32-chunks of [32k x 128m], each 8192 floats
// (hi plane 4096 + lo plane 4096).
// chunks 0-3: prep0, 4-7: prep1, 8-15: upd0 (K=256), 16-19: upd1
__device__ float g_Wfrag[20 * 8192];
__device__ float g_bp0[128];
__device__ float g_bp1[128];
__device__ float g_bu0[128];
__device__ float g_bu1[128];

__device__ float g_bufA[NN * 128];   // intermediate activations
__device__ float g_prep[NN * 128];   // prep FFN output (per-node messages)
__device__ float g_agg[NN * 128];    // aggregated sums
__device__ float g_cnt[NN];          // per-node edge counts

// ---------------- helpers ----------------
__device__ __forceinline__ float tf32_rna(float x) {
    uint32_t u;
    asm("cvt.rna.tf32.f32 %0, %1;" : "=r"(u) : "f"(x));
    return __uint_as_float(u);
}
__device__ __forceinline__ float gelu_f(float x) {
    return 0.5f * x * (1.0f + erff(x * 0.70710678118654752f));
}
// D += A(16x8 tf32, row) * B(8x8 tf32, col)
__device__ __forceinline__ void mma_tf32(float* c, float4 a, float bx, float by) {
    asm("mma.sync.aligned.m16n8k8.row.col.f32.tf32.tf32.f32 "
        "{%0,%1,%2,%3},{%4,%5,%6,%7},{%8,%9},{%0,%1,%2,%3};"
        : "+f"(c[0]), "+f"(c[1]), "+f"(c[2]), "+f"(c[3])
        : "r"(__float_as_uint(a.x)), "r"(__float_as_uint(a.y)),
          "r"(__float_as_uint(a.z)), "r"(__float_as_uint(a.w)),
          "r"(__float_as_uint(bx)), "r"(__float_as_uint(by)));
}

// ---------------- fold W into tf32 hi/lo fragment planes (K32 chunks) ----------------
// Entry idx within chunk: idx = (ks*8 + mt)*32 + lane, ks in 0..3, mt in 0..7.
// a0=(r0,k0) a1=(r1,k0) a2=(r0,k1) a3=(r1,k1);
// r0 = mt*16 + lane/4, r1 = r0+8, k0 = ks*8 + lane%4 (chunk-local), k1 = k0+4.
// hi plane at chunkbase + idx*4, lo plane at chunkbase + 4096 + idx*4.
__global__ void fold_frag(
    const float* __restrict__ W0, const float* __restrict__ g0, const float* __restrict__ v0,
    const float* __restrict__ W1, const float* __restrict__ g1, const float* __restrict__ v1,
    const float* __restrict__ W2, const float* __restrict__ g2, const float* __restrict__ v2,
    const float* __restrict__ W3, const float* __restrict__ g3, const float* __restrict__ v3) {
    int t = blockIdx.x * 256 + threadIdx.x;   // 0 .. 20479
    int chunk = t >> 10;                      // 0..19
    int idx = t & 1023;
    const float *W, *g, *v;
    int koff;
    if (chunk < 4)       { W = W0; g = g0; v = v0; koff = chunk * 32; }
    else if (chunk < 8)  { W = W1; g = g1; v = v1; koff = (chunk - 4) * 32; }
    else if (chunk < 16) { W = W2; g = g2; v = v2; koff = (chunk - 8) * 32; }
    else                 { W = W3; g = g3; v = v3; koff = (chunk - 16) * 32; }
    int lane = idx & 31;
    int mt = (idx >> 5) & 7;
    int ks = idx >> 8;                        // 0..3
    int r0 = mt * 16 + (lane >> 2);
    int r1 = r0 + 8;
    int kg0 = koff + ks * 8 + (lane & 3);
    int kg1 = kg0 + 4;
    float s0 = g[kg0] * rsqrtf(v[kg0] + BN_EPS);
    float s1 = g[kg1] * rsqrtf(v[kg1] + BN_EPS);
    float v00 = W[kg0 * 128 + r0] * s0;   // a0
    float v10 = W[kg0 * 128 + r1] * s0;   // a1
    float v01 = W[kg1 * 128 + r0] * s1;   // a2
    float v11 = W[kg1 * 128 + r1] * s1;   // a3
    float h00 = tf32_rna(v00), h10 = tf32_rna(v10), h01 = tf32_rna(v01), h11 = tf32_rna(v11);
    float l00 = tf32_rna(v00 - h00), l10 = tf32_rna(v10 - h10);
    float l01 = tf32_rna(v01 - h01), l11 = tf32_rna(v11 - h11);
    float* base = g_Wfrag + chunk * 8192;
    *reinterpret_cast<float4*>(base + idx * 4)        = make_float4(h00, h10, h01, h11);
    *reinterpret_cast<float4*>(base + 4096 + idx * 4) = make_float4(l00, l10, l01, l11);
}

// b'[j] = bias[j] + sum_i (b_i - m_i*s_i) * W[i][j]
__global__ void fold_b_all(
    const float* __restrict__ g0, const float* __restrict__ b0, const float* __restrict__ m0, const float* __restrict__ v0, const float* __restrict__ W0, const float* __restrict__ s0, float* __restrict__ o0,
    const float* __restrict__ g1, const float* __restrict__ b1, const float* __restrict__ m1, const float* __restrict__ v1, const float* __restrict__ W1, const float* __restrict__ s1, float* __restrict__ o1,
    const float* __restrict__ g2, const float* __restrict__ b2, const float* __restrict__ m2, const float* __restrict__ v2, const float* __restrict__ W2, const float* __restrict__ s2, float* __restrict__ o2,
    const float* __restrict__ g3, const float* __restrict__ b3, const float* __restrict__ m3, const float* __restrict__ v3, const float* __restrict__ W3, const float* __restrict__ s3, float* __restrict__ o3) {
    int l = blockIdx.x;
    const float *g, *b, *m, *v, *W, *s;
    float* o;
    int K;
    switch (l) {
        case 0:  g = g0; b = b0; m = m0; v = v0; W = W0; s = s0; o = o0; K = 128; break;
        case 1:  g = g1; b = b1; m = m1; v = v1; W = W1; s = s1; o = o1; K = 128; break;
        case 2:  g = g2; b = b2; m = m2; v = v2; W = W2; s = s2; o = o2; K = 256; break;
        default: g = g3; b = b3; m = m3; v = v3; W = W3; s = s3; o = o3; K = 128; break;
    }
    int j = threadIdx.x;
    float acc0 = s[j], acc1 = 0.f;
    #pragma unroll 8
    for (int i = 0; i < K; i += 2) {
        float sc0 = g[i] * rsqrtf(v[i] + BN_EPS);
        float sc1 = g[i + 1] * rsqrtf(v[i + 1] + BN_EPS);
        acc0 = fmaf(b[i] - m[i] * sc0, W[i * 128 + j], acc0);
        acc1 = fmaf(b[i + 1] - m[i + 1] * sc1, W[(i + 1) * 128 + j], acc1);
    }
    o[j] = acc0 + acc1;
}

// ---------------- zero agg + cnt ----------------
__global__ void zero_kernel() {
    int i = blockIdx.x * 256 + threadIdx.x;
    float4 z = make_float4(0.f, 0.f, 0.f, 0.f);
    if (i < NN * 128 / 4) reinterpret_cast<float4*>(g_agg)[i] = z;
    if (i < NN / 4)       reinterpret_cast<float4*>(g_cnt)[i] = z;
}

// ---------------- tensor-core GEMM + bias + gelu (3xTF32, K32 chunks, 2 blocks/SM) --
// Y[nrows,128] = gelu(X @ W' + b').
// Block: 256 threads, tile = 128 x-rows (N) x 128 w-cols (M). 84KB smem -> 2 blocks/SM,
// so one block's HMMA mainloop overlaps the other's staging/repack.
// Warps: mg = wid&3 (M stripe of 32), ng = wid>>2 (N stripe of 64).
template <int CHUNKS, bool CONCAT>
__global__ void __launch_bounds__(256, 2)
gemm_tc(const float* __restrict__ X0, const float* __restrict__ Wfrag,
        const float* __restrict__ B, float* __restrict__ Y, int nrows) {
    constexpr int LDS_X = 36;            // floats per staged x row (144B)
    extern __shared__ float sm[];
    float* ws = sm;                      // 8192 floats: W frag chunk (hi 4096 | lo 4096)
    float* xf = sm + 8192;               // 8192 floats: 2048 B-frag entries {b0h,b1h,b0l,b1l}
    float* xs = sm + 16384;              // 128 * 36 staging

    const int tid = threadIdx.x;
    const int lane = tid & 31;
    const int wid = tid >> 5;
    const int mg = wid & 3;              // M group (w-cols)
    const int ng = wid >> 2;             // N group (x-rows)
    const int row0 = blockIdx.x * 128;

    float c[2][8][4];
    #pragma unroll
    for (int mt = 0; mt < 2; mt++)
        #pragma unroll
        for (int nt = 0; nt < 8; nt++)
            #pragma unroll
            for (int j = 0; j < 4; j++) c[mt][nt][j] = 0.f;

    for (int cc = 0; cc < CHUNKS; cc++) {
        if (cc) __syncthreads();
        // ---- bulk-copy W frag chunk into smem (coalesced, fragment-ordered) ----
        {
            const float4* Wg = reinterpret_cast<const float4*>(Wfrag + cc * 8192);
            float4* Ws4 = reinterpret_cast<float4*>(ws);
            #pragma unroll
            for (int i = tid; i < 2048; i += 256) Ws4[i] = Wg[i];
        }
        // ---- stage x rows (coalesced, 32 k-columns of the source) ----
        {
            const float* Xc = (CONCAT && cc >= CHUNKS / 2) ? g_agg : X0;
            const int koff = (cc & 3) * 32;
            #pragma unroll
            for (int idx = tid; idx < 128 * 8; idx += 256) {
                int r = idx >> 3, k4 = idx & 7;
                int row = row0 + r;
                float4 v = make_float4(0.f, 0.f, 0.f, 0.f);
                if (row < nrows) {
                    v = reinterpret_cast<const float4*>(Xc + (size_t)row * 128 + koff)[k4];
                    if (CONCAT && cc >= CHUNKS / 2) {
                        float cn = g_cnt[row];
                        float f = (cn > 0.f) ? (1.0f / cn) : 0.f;
                        v.x *= f; v.y *= f; v.z *= f; v.w *= f;
                    }
                }
                *reinterpret_cast<float4*>(xs + r * LDS_X + k4 * 4) = v;
            }
        }
        __syncthreads();
        // ---- repack to B fragments with tf32 hi/lo split ----
        // entry e: le = e&31, nt = (e>>5)&15, ks = e>>9 (0..3)
        // b0 = x[nt*8 + le/4][ks*8 + le%4], b1 = same k+4
        #pragma unroll
        for (int e = tid; e < 2048; e += 256) {
            int le = e & 31, nt = (e >> 5) & 15, ks = e >> 9;
            int r = nt * 8 + (le >> 2);
            int k = ks * 8 + (le & 3);
            float v0 = xs[r * LDS_X + k];
            float v1 = xs[r * LDS_X + k + 4];
            float h0 = tf32_rna(v0), h1 = tf32_rna(v1);
            float l0 = tf32_rna(v0 - h0), l1 = tf32_rna(v1 - h1);
            *reinterpret_cast<float4*>(xf + e * 4) = make_float4(h0, h1, l0, l1);
        }
        __syncthreads();

        // ---- mainloop: 4 k-steps, A and B both from smem ----
        #pragma unroll
        for (int ks = 0; ks < 4; ks++) {
            float4 ah[2], al[2];
            #pragma unroll
            for (int mt = 0; mt < 2; mt++) {
                int aidx = (ks * 8 + mg * 2 + mt) * 32 + lane;
                ah[mt] = *reinterpret_cast<const float4*>(ws + aidx * 4);
                al[mt] = *reinterpret_cast<const float4*>(ws + 4096 + aidx * 4);
            }
            #pragma unroll
            for (int nt = 0; nt < 8; nt++) {
                float4 b = *reinterpret_cast<const float4*>(
                    xf + ((ks * 16 + ng * 8 + nt) * 32 + lane) * 4);
                #pragma unroll
                for (int mt = 0; mt < 2; mt++) {
                    mma_tf32(c[mt][nt], ah[mt], b.x, b.y);  // Ah * Bh
                    mma_tf32(c[mt][nt], ah[mt], b.z, b.w);  // Ah * Bl
                    mma_tf32(c[mt][nt], al[mt], b.x, b.y);  // Al * Bh
                }
            }
        }
    }

    // ---- epilogue: bias + gelu + transposed store ----
    #pragma unroll
    for (int mt = 0; mt < 2; mt++) {
        int col0 = mg * 32 + mt * 16 + (lane >> 2);
        float bb0 = B[col0];
        float bb8 = B[col0 + 8];
        #pragma unroll
        for (int nt = 0; nt < 8; nt++) {
            int rowx = row0 + ng * 64 + nt * 8 + 2 * (lane & 3);
            if (rowx < nrows) {
                Y[(size_t)rowx * 128 + col0]     = gelu_f(c[mt][nt][0] + bb0);
                Y[(size_t)rowx * 128 + col0 + 8] = gelu_f(c[mt][nt][2] + bb8);
            }
            if (rowx + 1 < nrows) {
                Y[(size_t)(rowx + 1) * 128 + col0]     = gelu_f(c[mt][nt][1] + bb0);
                Y[(size_t)(rowx + 1) * 128 + col0 + 8] = gelu_f(c[mt][nt][3] + bb8);
            }
        }
    }
}

// ---------------- edge scatter: 4 edges per warp, loads batched for MLP ----------------
__global__ void __launch_bounds__(256)
scatter_kernel(const int* __restrict__ edges, const float* __restrict__ ew) {
    int warp = blockIdx.x * 8 + (threadIdx.x >> 5);
    int lane = threadIdx.x & 31;
    int e0 = warp * 4;

    int dst[4], src[4];
    float w[4];
    #pragma unroll
    for (int t = 0; t < 4; t++) {
        dst[t] = __ldg(edges + e0 + t);
        src[t] = __ldg(edges + EE + e0 + t);
        w[t]   = __ldg(ew + e0 + t);
    }
    float4 v[4];
    #pragma unroll
    for (int t = 0; t < 4; t++)
        v[t] = __ldg(reinterpret_cast<const float4*>(g_prep + (size_t)src[t] * 128) + lane);
    #pragma unroll
    for (int t = 0; t < 4; t++) {
        v[t].x *= w[t]; v[t].y *= w[t]; v[t].z *= w[t]; v[t].w *= w[t];
        float* dp = g_agg + (size_t)dst[t] * 128 + lane * 4;
        asm volatile("red.global.add.v4.f32 [%0], {%1, %2, %3, %4};"
                     :: "l"(dp), "f"(v[t].x), "f"(v[t].y), "f"(v[t].z), "f"(v[t].w) : "memory");
    }
    if (lane < 4) {
        asm volatile("red.global.add.f32 [%0], %1;"
                     :: "l"(g_cnt + dst[lane]), "f"(1.0f) : "memory");
    }
}

// ---------------- launch ----------------
extern "C" void kernel_launch(void* const* d_in, const int* in_sizes, int n_in,
                              void* d_out, int out_size) {
    const float* node_repr = (const float*)d_in[0];
    const int*   edges     = (const int*)d_in[1];
    const float* edge_w    = (const float*)d_in[2];

    const float* p0g = (const float*)d_in[3];  const float* p0b = (const float*)d_in[4];
    const float* p0m = (const float*)d_in[5];  const float* p0v = (const float*)d_in[6];
    const float* p0W = (const float*)d_in[7];  const float* p0bias = (const float*)d_in[8];
    const float* p1g = (const float*)d_in[9];  const float* p1b = (const float*)d_in[10];
    const float* p1m = (const float*)d_in[11]; const float* p1v = (const float*)d_in[12];
    const float* p1W = (const float*)d_in[13]; const float* p1bias = (const float*)d_in[14];
    const float* u0g = (const float*)d_in[15]; const float* u0b = (const float*)d_in[16];
    const float* u0m = (const float*)d_in[17]; const float* u0v = (const float*)d_in[18];
    const float* u0W = (const float*)d_in[19]; const float* u0bias = (const float*)d_in[20];
    const float* u1g = (const float*)d_in[21]; const float* u1b = (const float*)d_in[22];
    const float* u1m = (const float*)d_in[23]; const float* u1v = (const float*)d_in[24];
    const float* u1W = (const float*)d_in[25]; const float* u1bias = (const float*)d_in[26];

    float *pWfrag, *pbp0, *pbp1, *pbu0, *pbu1, *pBufA, *pPrep;
    cudaGetSymbolAddress((void**)&pWfrag, g_Wfrag);
    cudaGetSymbolAddress((void**)&pbp0, g_bp0);
    cudaGetSymbolAddress((void**)&pbp1, g_bp1);
    cudaGetSymbolAddress((void**)&pbu0, g_bu0);
    cudaGetSymbolAddress((void**)&pbu1, g_bu1);
    cudaGetSymbolAddress((void**)&pBufA, g_bufA);
    cudaGetSymbolAddress((void**)&pPrep, g_prep);

    const int smemB = (8192 + 8192 + 128 * 36) * 4;   // 83968 B -> 2 blocks/SM
    cudaFuncSetAttribute(gemm_tc<4, false>, cudaFuncAttributeMaxDynamicSharedMemorySize, smemB);
    cudaFuncSetAttribute(gemm_tc<8, true>,  cudaFuncAttributeMaxDynamicSharedMemorySize, smemB);

    // 1) fold BN + tf32 hi/lo split into K32-chunk fragment planes, fold biases
    fold_frag<<<80, 256>>>(p0W, p0g, p0v,
                           p1W, p1g, p1v,
                           u0W, u0g, u0v,
                           u1W, u1g, u1v);
    fold_b_all<<<4, 128>>>(p0g, p0b, p0m, p0v, p0W, p0bias, pbp0,
                           p1g, p1b, p1m, p1v, p1W, p1bias, pbp1,
                           u0g, u0b, u0m, u0v, u0W, u0bias, pbu0,
                           u1g, u1b, u1m, u1v, u1W, u1bias, pbu1);

    // 2) zero aggregation buffers
    zero_kernel<<<(NN * 128 / 4 + 255) / 256, 256>>>();

    const int gblocks = (NN + 127) / 128;  // 391
    // 3) prepare FFN per NODE (16x algebraic reduction vs per-edge)
    gemm_tc<4, false><<<gblocks, 256, smemB>>>(node_repr, pWfrag,             pbp0, pBufA, NN);
    gemm_tc<4, false><<<gblocks, 256, smemB>>>(pBufA,     pWfrag + 4 * 8192,  pbp1, pPrep, NN);

    // 4) scatter-aggregate along edges
    scatter_kernel<<<EE / 32, 256>>>(edges, edge_w);

    // 5) update FFN: concat(node_repr, agg_mean) -> H, then H -> H (writes d_out)
    gemm_tc<8, true><<<gblocks, 256, smemB>>>(node_repr, pWfrag + 8 * 8192,   pbu0, pBufA, NN);
    gemm_tc<4, false><<<gblocks, 256, smemB>>>(pBufA,    pWfrag + 16 * 8192,  pbu1, (float*)d_out, NN);
}